// round 16
// baseline (speedup 1.0000x reference)
#include <cuda_runtime.h>
#include <cuda_bf16.h>
#include <cstdint>

// Problem constants
#define B_  512
#define T_  512
#define NQ_ 1000
#define K_  5
#define M_  50
#define DK_ 64
#define DV_ 256
#define DF_ 50
#define BT_ (B_*T_)   // 262144

// ---------------- scratch (device globals; no allocation allowed) ----------------
__device__ __align__(16) float g_Tw   [(NQ_+1)*M_];
__device__ __align__(16) float g_Tsq  [(NQ_+1)*DF_];
__device__ __align__(16) float g_Tbeta[(NQ_+1)*4];
__device__ __align__(16) float g_Tdisc[(NQ_+1)];
__device__ __align__(16) float g_Tcorn[(NQ_+1)*4];
__device__ __align__(16) float g_E1[NQ_*DV_], g_E2[NQ_*DV_];
__device__ __align__(16) float g_A1[NQ_*DV_], g_A2[NQ_*DV_];
__device__ __align__(16) float g_be[DV_], g_ba[DV_];
__device__ __align__(16) float g_Te[(NQ_+1)*K_*DV_];
__device__ __align__(16) float g_Ta[(NQ_+1)*K_*DV_];
__device__ __align__(16) __nv_bfloat16 g_readsh[BT_*DV_];   // 134 MB (bf16)

__device__ __forceinline__ float sigmoidf_(float x) { return 1.f/(1.f+expf(-x)); }

// ---- packed f32x2 helpers ----
typedef unsigned long long ull;
__device__ __forceinline__ ull fma2(ull a, ull b, ull c) {
    ull d; asm("fma.rn.f32x2 %0, %1, %2, %3;" : "=l"(d) : "l"(a), "l"(b), "l"(c));
    return d;
}
__device__ __forceinline__ ull add2(ull a, ull b) {
    ull d; asm("add.rn.f32x2 %0, %1, %2;" : "=l"(d) : "l"(a), "l"(b));
    return d;
}
__device__ __forceinline__ ull pack2(float lo, float hi) {
    ull d; asm("mov.b64 %0, {%1, %2};" : "=l"(d) : "f"(lo), "f"(hi));
    return d;
}
__device__ __forceinline__ void unpack2(ull v, float& lo, float& hi) {
    asm("mov.b64 {%0, %1}, %2;" : "=f"(lo), "=f"(hi) : "l"(v));
}
__device__ __forceinline__ uint32_t bf16x2_(float lo, float hi) {
    uint32_t r;
    asm("cvt.rn.bf16x2.f32 %0, %1, %2;" : "=r"(r) : "f"(hi), "f"(lo));
    return r;
}

// ---------------- P0: effective biases ----------------
__global__ void p0_bias(const float* __restrict__ vb,
                        const float* __restrict__ We, const float* __restrict__ eb,
                        const float* __restrict__ Wa, const float* __restrict__ ab) {
    __shared__ float svb[DV_];
    int tid = threadIdx.x;
    svb[tid] = vb[tid];
    __syncthreads();
    float e = eb[tid], a = ab[tid];
    for (int k = 0; k < DV_; k++) {
        float x = svb[k];
        e = fmaf(x, We[k*DV_+tid], e);
        a = fmaf(x, Wa[k*DV_+tid], a);
    }
    g_be[tid] = e; g_ba[tid] = a;
}

// ---------------- P2: value_W @ {erase_W, add_W} ----------------
__global__ void p2_etables(const float* __restrict__ vW,
                           const float* __restrict__ We, const float* __restrict__ Wa) {
    __shared__ float vr1[8][DV_];
    __shared__ float vr2[8][DV_];
    int tid = threadIdx.x;
    int i0 = blockIdx.x * 8;
    #pragma unroll
    for (int i = 0; i < 8; i++) {
        vr1[i][tid] = vW[(i0+i)*DV_ + tid];
        vr2[i][tid] = vW[(NQ_ + i0+i)*DV_ + tid];
    }
    __syncthreads();
    float e1[8] = {0}, e2[8] = {0}, a1[8] = {0}, a2[8] = {0};
    int v = tid;
    for (int k = 0; k < DV_; k++) {
        float we = We[k*DV_ + v];
        float wa = Wa[k*DV_ + v];
        #pragma unroll
        for (int i = 0; i < 8; i++) {
            float x1 = vr1[i][k], x2 = vr2[i][k];
            e1[i] = fmaf(x1, we, e1[i]); e2[i] = fmaf(x2, we, e2[i]);
            a1[i] = fmaf(x1, wa, a1[i]); a2[i] = fmaf(x2, wa, a2[i]);
        }
    }
    #pragma unroll
    for (int i = 0; i < 8; i++) {
        g_E1[(i0+i)*DV_ + v] = e1[i]; g_E2[(i0+i)*DV_ + v] = e2[i];
        g_A1[(i0+i)*DV_ + v] = a1[i]; g_A2[(i0+i)*DV_ + v] = a2[i];
    }
}

// ---------------- P13: merged per-(q,r) activation tables + per-q tables ----------
__global__ void p13_kernel(const float* __restrict__ qW, const float* __restrict__ Mk,
                           const float* __restrict__ sW,
                           const float* __restrict__ tW, const float* __restrict__ tb,
                           const float* __restrict__ dW, const float* __restrict__ db,
                           const float* __restrict__ cW, const float* __restrict__ cb) {
    int tid = threadIdx.x;
    if (blockIdx.x < (NQ_+1)*K_) {
        int q = blockIdx.x / K_, r = blockIdx.x % K_;
        int v = tid;
        float rs = (float)r * 0.25f;
        float pe = 0.f, pa = 0.f;
        if (q > 0) {
            int idx = q - 1;
            pe = fmaf(rs, g_E2[idx*DV_ + v], g_E1[idx*DV_ + v]);
            pa = fmaf(rs, g_A2[idx*DV_ + v], g_A1[idx*DV_ + v]);
        }
        pe += g_be[v]; pa += g_ba[v];
        int base = (q*K_ + r)*DV_ + v;
        g_Te[base] = sigmoidf_(pe);
        g_Ta[base] = tanhf(pa);
        return;
    }
    __shared__ float qe[DK_];
    __shared__ float wl[M_];
    __shared__ float red[2];
    int q = blockIdx.x - (NQ_+1)*K_;
    if (tid < DK_) qe[tid] = qW[q*DK_ + tid];
    __syncthreads();
    if (tid < 50) {
        float acc = 0.f;
        const float* mk = Mk + tid*DK_;
        #pragma unroll 16
        for (int k = 0; k < DK_; k++) acc = fmaf(qe[k], mk[k], acc);
        wl[tid] = acc;
    } else if (tid < 100) {
        int j = tid - 50; float acc = 0.f;
        for (int k = 0; k < DK_; k++) acc = fmaf(qe[k], sW[(DV_+k)*DF_ + j], acc);
        g_Tsq[q*DF_ + j] = acc;
    } else if (tid < 104) {
        int c = tid - 100; float acc = tb[c];
        for (int k = 0; k < DK_; k++) acc = fmaf(qe[k], tW[k*4 + c], acc);
        g_Tbeta[q*4 + c] = acc;
    } else if (tid == 104) {
        float acc = db[0];
        for (int k = 0; k < DK_; k++) acc = fmaf(qe[k], dW[50 + k], acc);
        g_Tdisc[q] = acc;
    } else if (tid < 109) {
        int c = tid - 105; float acc = cb[c];
        for (int k = 0; k < DK_; k++) acc = fmaf(qe[k], cW[(50+k)*4 + c], acc);
        g_Tcorn[q*4 + c] = acc;
    }
    __syncthreads();
    if (tid == 0) {
        float mx = wl[0];
        for (int m = 1; m < M_; m++) mx = fmaxf(mx, wl[m]);
        red[0] = mx;
    }
    __syncthreads();
    if (tid < M_) wl[tid] = expf(wl[tid] - red[0]);
    __syncthreads();
    if (tid == 0) {
        float s = 0.f;
        for (int m = 0; m < M_; m++) s += wl[m];
        red[1] = 1.f / s;
    }
    __syncthreads();
    if (tid < M_) g_Tw[q*M_ + tid] = wl[tid] * red[1];
}

// ---------------- Scan v7: 2-way m-split, 256 thr, 50% occ target ----------------
// Thread (vp = tid>>1, mh = tid&1): owns v = vb*128+vp and m range [26*mh, 26*mh+26)
// as 13 packed pairs (M padded 50->52, pad w=0, pad Mv=0).
// w buffers: warp-private, 128B-aligned, interleaved [j][mh] (8B each) so each
// per-j LDS.64 touches one 128B line -> 1 wavefront (same MIO as v6).
// Reduction: shfl_xor(1); mh=0 lanes store bf16 (contiguous 32B per warp).
__global__ __launch_bounds__(256, 4) void scan_kernel(const int* __restrict__ qd,
                                                      const int* __restrict__ rd,
                                                      const float* __restrict__ Mv0) {
    __shared__ __align__(128) ull w2[8][2][32];   // [warp][buf][2*j+mh], 26 used
    int b    = blockIdx.y;
    int vb   = blockIdx.x;
    int tid  = threadIdx.x;
    int warp = tid >> 5;
    int lane = tid & 31;
    int vp   = (warp << 4) + (lane >> 1);
    int mh   = lane & 1;
    int v    = vb*128 + vp;
    int m0   = 26*mh;

    ull Mv2[13];
    #pragma unroll
    for (int j = 0; j < 13; j++) {
        int m = m0 + 2*j;
        Mv2[j] = (m < M_) ? pack2(Mv0[m*DV_ + v], Mv0[(m+1)*DV_ + v]) : 0ull;
    }

    const int bT = b * T_;
    const int* qp = qd + bT;
    const int* rp = rd + bT;
    __nv_bfloat16* rout = g_readsh + (size_t)bT * DV_ + v;

    // staging roles: lanes 0-12 -> (j=lane, mh=0); lanes 13-24 -> (j=lane-13, mh=1);
    // lane 25 -> (j=12, mh=1) zero pad. Others idle.
    bool st = (lane < 26);
    bool ld = (lane < 25);
    int sidx = (lane < 13) ? (2*lane) : (2*(lane-13) + 1);
    int soff = (lane < 13) ? (2*lane) : (26 + 2*(lane-13));

    int q0 = __ldg(qp+0), r0 = __ldg(rp+0);
    int q1 = __ldg(qp+1), r1 = __ldg(rp+1);
    int q2 = __ldg(qp+2), r2 = __ldg(rp+2);
    int q3 = __ldg(qp+3), r3 = __ldg(rp+3);

    ull wA = 0ull, wB = 0ull;
    if (st) {
        w2[warp][0][sidx] = ld ? *(const ull*)&g_Tw[q0*M_ + soff] : 0ull;
        if (ld) {
            wA = *(const ull*)&g_Tw[q1*M_ + soff];
            wB = *(const ull*)&g_Tw[q2*M_ + soff];
        }
    }
    float eA = g_Te[(q0*K_ + r0)*DV_ + v];
    float aA = g_Ta[(q0*K_ + r0)*DV_ + v];
    float eB = g_Te[(q1*K_ + r1)*DV_ + v];
    float aB = g_Ta[(q1*K_ + r1)*DV_ + v];

    for (int t = 0; t < T_; t++) {
        // stage w(t+1); advance register pipeline (w(t+3) load)
        if (st) w2[warp][(t+1)&1][sidx] = wA;
        wA = wB;
        if (ld) wB = *(const ull*)&g_Tw[q3*M_ + soff];
        ull ne2 = pack2(-eA, -eA);
        ull a2  = pack2(aA,  aA);
        eA = eB; aA = aB;
        {
            int basen = (q2*K_ + r2)*DV_ + v;
            eB = g_Te[basen];
            aB = g_Ta[basen];
        }
        q2 = q3; r2 = r3;
        {
            int tn = t + 4; if (tn > T_-1) tn = T_-1;
            q3 = __ldg(qp + tn); r3 = __ldg(rp + tn);
        }
        __syncwarp(0xffffffffu);

        const ull* wb = &w2[warp][t & 1][0];
        ull acc0 = 0ull, acc1 = 0ull;
        #pragma unroll
        for (int j = 0; j < 12; j += 2) {
            ull wv0 = wb[2*j + mh];
            ull wv1 = wb[2*(j+1) + mh];
            {
                ull old = Mv2[j];
                acc0 = fma2(wv0, old, acc0);
                ull t1 = fma2(old, ne2, a2);
                Mv2[j] = fma2(wv0, t1, old);
            }
            {
                ull old = Mv2[j+1];
                acc1 = fma2(wv1, old, acc1);
                ull t1 = fma2(old, ne2, a2);
                Mv2[j+1] = fma2(wv1, t1, old);
            }
        }
        {   // j = 12
            ull wv = wb[24 + mh];
            ull old = Mv2[12];
            acc0 = fma2(wv, old, acc0);
            ull t1 = fma2(old, ne2, a2);
            Mv2[12] = fma2(wv, t1, old);
        }
        float lo, hi;
        unpack2(add2(acc0, acc1), lo, hi);
        float s = lo + hi;
        s += __shfl_xor_sync(0xffffffffu, s, 1);
        if (mh == 0)
            rout[(size_t)t * DV_] = __float2bfloat16(s);
    }
}

// ---------------- Summary GEMM v5 (R15-proven, 99us): bf16 m16n8k16 + heads ------
#define ASTR 20
#define BTSTR 20
#define ABUF_U32 (128*ASTR)               // 2560
#define BBUF_U32 (64*BTSTR)               // 1280
#define SSUM_U32 (128*53)                 // 6784
#define POOL_U32 SSUM_U32
__global__ __launch_bounds__(256, 2) void summary_heads(const float* __restrict__ sW,
                                                        const float* __restrict__ sb,
                                                        const int* __restrict__ qd,
                                                        const float* __restrict__ abW,
                                                        const float* __restrict__ abB,
                                                        const float* __restrict__ dW,
                                                        const float* __restrict__ cW,
                                                        float* __restrict__ out) {
    __shared__ __align__(16) uint32_t pool[POOL_U32];
    __shared__ float sAb[DF_], sDw[DF_], sCw[DF_*4];
    uint32_t* As = pool;
    uint32_t* Bt = pool + ABUF_U32;
    float* sSum = (float*)pool;
    int tid = threadIdx.x;
    int w = tid >> 5, lane = tid & 31;
    int g = lane >> 2, t = lane & 3;
    int row0 = blockIdx.x * 128;

    if (tid < DF_)  { sAb[tid] = abW[tid]; sDw[tid] = dW[tid]; }
    if (tid < DF_*4) sCw[tid] = cW[tid];

    float acc[8][4];
    #pragma unroll
    for (int j = 0; j < 8; j++)
        #pragma unroll
        for (int c = 0; c < 4; c++) acc[j][c] = 0.f;

    int arow = tid >> 1, ahalf = (tid & 1) * 8;
    const uint32_t* agsrc = (const uint32_t*)(g_readsh + (size_t)(row0 + arow)*DV_) + ahalf;
    int bn = tid >> 2, bkp0 = (tid & 3) * 4;
    uint4 arv[2];
    uint32_t brv[4];

    arv[0] = *(const uint4*)(agsrc);
    arv[1] = *(const uint4*)(agsrc + 4);
    {
        #pragma unroll
        for (int u = 0; u < 4; u++) {
            int kk = 2*(bkp0 + u);
            float b0 = (bn < DF_) ? sW[kk*DF_ + bn] : 0.f;
            float b1 = (bn < DF_) ? sW[(kk+1)*DF_ + bn] : 0.f;
            brv[u] = bf16x2_(b0, b1);
        }
    }

    for (int ki = 0; ki < 8; ki++) {
        *(uint4*)(As + arow*ASTR + ahalf)     = arv[0];
        *(uint4*)(As + arow*ASTR + ahalf + 4) = arv[1];
        *(uint4*)(Bt + bn*BTSTR + bkp0)       = make_uint4(brv[0], brv[1], brv[2], brv[3]);
        __syncthreads();

        if (ki + 1 < 8) {
            const uint32_t* srcn = agsrc + (ki + 1)*16;
            arv[0] = *(const uint4*)(srcn);
            arv[1] = *(const uint4*)(srcn + 4);
            int k0n = (ki + 1) * 32;
            #pragma unroll
            for (int u = 0; u < 4; u++) {
                int kk = k0n + 2*(bkp0 + u);
                float b0 = (bn < DF_) ? sW[kk*DF_ + bn] : 0.f;
                float b1 = (bn < DF_) ? sW[(kk+1)*DF_ + bn] : 0.f;
                brv[u] = bf16x2_(b0, b1);
            }
        }

        #pragma unroll
        for (int s = 0; s < 2; s++) {
            int kp = 8*s;
            uint32_t a0 = As[(w*16 + g    )*ASTR + kp + t];
            uint32_t a1 = As[(w*16 + g + 8)*ASTR + kp + t];
            uint32_t a2 = As[(w*16 + g    )*ASTR + kp + t + 4];
            uint32_t a3 = As[(w*16 + g + 8)*ASTR + kp + t + 4];
            #pragma unroll
            for (int j = 0; j < 8; j++) {
                uint32_t b0 = Bt[(8*j + g)*BTSTR + kp + t];
                uint32_t b1 = Bt[(8*j + g)*BTSTR + kp + t + 4];
                asm volatile(
                    "mma.sync.aligned.m16n8k16.row.col.f32.bf16.bf16.f32 "
                    "{%0,%1,%2,%3}, {%4,%5,%6,%7}, {%8,%9}, {%0,%1,%2,%3};"
                    : "+f"(acc[j][0]), "+f"(acc[j][1]), "+f"(acc[j][2]), "+f"(acc[j][3])
                    : "r"(a0), "r"(a1), "r"(a2), "r"(a3), "r"(b0), "r"(b1));
            }
        }
        __syncthreads();
    }

    {
        int rA = w*16 + g, rB = rA + 8;
        int qA = qd[row0 + rA], qB = qd[row0 + rB];
        const float* tsqA = g_Tsq + qA*DF_;
        const float* tsqB = g_Tsq + qB*DF_;
        #pragma unroll
        for (int j = 0; j < 8; j++) {
            int n0 = 8*j + 2*t;
            #pragma unroll
            for (int c = 0; c < 2; c++) {
                int n = n0 + c;
                if (n < DF_) {
                    float bias = sb[n];
                    sSum[rA*53 + n] = tanhf(acc[j][c]     + tsqA[n] + bias);
                    sSum[rB*53 + n] = tanhf(acc[j][2 + c] + tsqB[n] + bias);
                }
            }
        }
    }
    __syncthreads();

    if (tid < 128) {
        int i = row0 + tid;
        int q = qd[i];
        float th = 0.f, ap = 0.f, l0 = 0.f, l1 = 0.f, l2 = 0.f, l3 = 0.f;
        #pragma unroll 10
        for (int k = 0; k < DF_; k++) {
            float s = sSum[tid*53 + k];
            th = fmaf(s, sAb[k], th);
            ap = fmaf(s, sDw[k], ap);
            l0 = fmaf(s, sCw[k*4+0], l0);
            l1 = fmaf(s, sCw[k*4+1], l1);
            l2 = fmaf(s, sCw[k*4+2], l2);
            l3 = fmaf(s, sCw[k*4+3], l3);
        }
        float theta = (th + __ldg(abB)) * 3.0f;
        ap += g_Tdisc[q];
        float alpha = (ap > 20.f) ? ap : log1pf(expf(ap));
        float4 tc = *(const float4*)&g_Tcorn[q*4];
        l0 += tc.x; l1 += tc.y; l2 += tc.z; l3 += tc.w;
        float cp0 = sigmoidf_(l0);
        float cp1 = cp0 * sigmoidf_(l1);
        float cp2 = cp1 * sigmoidf_(l2);
        float cp3 = cp2 * sigmoidf_(l3);
        const int BT = BT_;
        out[i] = theta;
        *(float4*)&out[BT + 4*i] = *(const float4*)&g_Tbeta[q*4];
        out[5*BT + i] = alpha;
        float* pp = out + 6*BT + 5*i;
        pp[0] = 1.f - cp0; pp[1] = cp0 - cp1; pp[2] = cp1 - cp2;
        pp[3] = cp2 - cp3; pp[4] = cp3;
        *(float4*)&out[11*BT + 4*i] = make_float4(l0, l1, l2, l3);
    }
}

// ---------------- launch ----------------
extern "C" void kernel_launch(void* const* d_in, const int* in_sizes, int n_in,
                              void* d_out, int out_size) {
    const int*   q_data    = (const int*)  d_in[0];
    const int*   r_data    = (const int*)  d_in[1];
    const float* q_embed_W = (const float*)d_in[2];
    const float* Mk        = (const float*)d_in[3];
    const float* Mv0       = (const float*)d_in[4];
    const float* value_W   = (const float*)d_in[5];
    const float* value_b   = (const float*)d_in[6];
    const float* erase_W   = (const float*)d_in[7];
    const float* erase_b   = (const float*)d_in[8];
    const float* add_W     = (const float*)d_in[9];
    const float* add_b     = (const float*)d_in[10];
    const float* summary_W = (const float*)d_in[11];
    const float* summary_b = (const float*)d_in[12];
    const float* ability_W = (const float*)d_in[13];
    const float* ability_b = (const float*)d_in[14];
    const float* thresh_W  = (const float*)d_in[15];
    const float* thresh_b  = (const float*)d_in[16];
    const float* disc_W    = (const float*)d_in[17];
    const float* disc_b    = (const float*)d_in[18];
    const float* corn_W    = (const float*)d_in[19];
    const float* corn_b    = (const float*)d_in[20];
    float* out = (float*)d_out;

    // Launch order: scan_kernel is my 4th launch -> ncu capture slot.
    p0_bias<<<1, 256>>>(value_b, erase_W, erase_b, add_W, add_b);
    p2_etables<<<125, 256>>>(value_W, erase_W, add_W);
    p13_kernel<<<(NQ_+1)*K_ + (NQ_+1), 256>>>(q_embed_W, Mk, summary_W,
                                              thresh_W, thresh_b, disc_W, disc_b,
                                              corn_W, corn_b);
    scan_kernel<<<dim3(2, B_), 256>>>(q_data, r_data, Mv0);
    summary_heads<<<BT_/128, 256>>>(summary_W, summary_b, q_data,
                                    ability_W, ability_b, disc_W, corn_W, out);
}

// round 17
// speedup vs baseline: 1.5241x; 1.5241x over previous
#include <cuda_runtime.h>
#include <cuda_bf16.h>
#include <cstdint>

// Problem constants
#define B_  512
#define T_  512
#define NQ_ 1000
#define K_  5
#define M_  50
#define DK_ 64
#define DV_ 256
#define DF_ 50
#define BT_ (B_*T_)   // 262144

// ---------------- scratch (device globals; no allocation allowed) ----------------
__device__ __align__(16) float g_Tw   [(NQ_+1)*M_];
__device__ __align__(16) float g_Tsq  [(NQ_+1)*DF_];
__device__ __align__(16) float g_Tbeta[(NQ_+1)*4];
__device__ __align__(16) float g_Tdisc[(NQ_+1)];
__device__ __align__(16) float g_Tcorn[(NQ_+1)*4];
__device__ __align__(16) float g_E1[NQ_*DV_], g_E2[NQ_*DV_];
__device__ __align__(16) float g_A1[NQ_*DV_], g_A2[NQ_*DV_];
__device__ __align__(16) float g_be[DV_], g_ba[DV_];
__device__ __align__(16) float g_Te[(NQ_+1)*K_*DV_];
__device__ __align__(16) float g_Ta[(NQ_+1)*K_*DV_];
__device__ __align__(16) __nv_bfloat16 g_readsh[BT_*DV_];   // 134 MB (bf16)

__device__ __forceinline__ float sigmoidf_(float x) { return 1.f/(1.f+expf(-x)); }

// ---- packed f32x2 helpers ----
typedef unsigned long long ull;
__device__ __forceinline__ ull fma2(ull a, ull b, ull c) {
    ull d; asm("fma.rn.f32x2 %0, %1, %2, %3;" : "=l"(d) : "l"(a), "l"(b), "l"(c));
    return d;
}
__device__ __forceinline__ ull add2(ull a, ull b) {
    ull d; asm("add.rn.f32x2 %0, %1, %2;" : "=l"(d) : "l"(a), "l"(b));
    return d;
}
__device__ __forceinline__ ull pack2(float lo, float hi) {
    ull d; asm("mov.b64 %0, {%1, %2};" : "=l"(d) : "f"(lo), "f"(hi));
    return d;
}
__device__ __forceinline__ void unpack2(ull v, float& lo, float& hi) {
    asm("mov.b64 {%0, %1}, %2;" : "=f"(lo), "=f"(hi) : "l"(v));
}
__device__ __forceinline__ uint32_t bf16x2_(float lo, float hi) {
    uint32_t r;
    asm("cvt.rn.bf16x2.f32 %0, %1, %2;" : "=r"(r) : "f"(hi), "f"(lo));
    return r;
}

// ---------------- P2': value_W @ {erase_W, add_W}, plus bias block ----------------
__global__ void p2_etables(const float* __restrict__ vW,
                           const float* __restrict__ We, const float* __restrict__ Wa,
                           const float* __restrict__ vb, const float* __restrict__ eb,
                           const float* __restrict__ ab) {
    __shared__ float vr1[8][DV_];
    __shared__ float vr2[8][DV_];
    int tid = threadIdx.x;
    if (blockIdx.x == 125) {            // bias path
        __shared__ float svb[DV_];
        svb[tid] = vb[tid];
        __syncthreads();
        float e = eb[tid], a = ab[tid];
        for (int k = 0; k < DV_; k++) {
            float x = svb[k];
            e = fmaf(x, We[k*DV_+tid], e);
            a = fmaf(x, Wa[k*DV_+tid], a);
        }
        g_be[tid] = e; g_ba[tid] = a;
        return;
    }
    int i0 = blockIdx.x * 8;
    #pragma unroll
    for (int i = 0; i < 8; i++) {
        vr1[i][tid] = vW[(i0+i)*DV_ + tid];
        vr2[i][tid] = vW[(NQ_ + i0+i)*DV_ + tid];
    }
    __syncthreads();
    float e1[8] = {0}, e2[8] = {0}, a1[8] = {0}, a2[8] = {0};
    int v = tid;
    for (int k = 0; k < DV_; k++) {
        float we = We[k*DV_ + v];
        float wa = Wa[k*DV_ + v];
        #pragma unroll
        for (int i = 0; i < 8; i++) {
            float x1 = vr1[i][k], x2 = vr2[i][k];
            e1[i] = fmaf(x1, we, e1[i]); e2[i] = fmaf(x2, we, e2[i]);
            a1[i] = fmaf(x1, wa, a1[i]); a2[i] = fmaf(x2, wa, a2[i]);
        }
    }
    #pragma unroll
    for (int i = 0; i < 8; i++) {
        g_E1[(i0+i)*DV_ + v] = e1[i]; g_E2[(i0+i)*DV_ + v] = e2[i];
        g_A1[(i0+i)*DV_ + v] = a1[i]; g_A2[(i0+i)*DV_ + v] = a2[i];
    }
}

// ---------------- P13: merged per-(q,r) activation tables + per-q tables ----------
__global__ void p13_kernel(const float* __restrict__ qW, const float* __restrict__ Mk,
                           const float* __restrict__ sW,
                           const float* __restrict__ tW, const float* __restrict__ tb,
                           const float* __restrict__ dW, const float* __restrict__ db,
                           const float* __restrict__ cW, const float* __restrict__ cb) {
    int tid = threadIdx.x;
    if (blockIdx.x < (NQ_+1)*K_) {
        int q = blockIdx.x / K_, r = blockIdx.x % K_;
        int v = tid;
        float rs = (float)r * 0.25f;
        float pe = 0.f, pa = 0.f;
        if (q > 0) {
            int idx = q - 1;
            pe = fmaf(rs, g_E2[idx*DV_ + v], g_E1[idx*DV_ + v]);
            pa = fmaf(rs, g_A2[idx*DV_ + v], g_A1[idx*DV_ + v]);
        }
        pe += g_be[v]; pa += g_ba[v];
        int base = (q*K_ + r)*DV_ + v;
        g_Te[base] = sigmoidf_(pe);
        g_Ta[base] = tanhf(pa);
        return;
    }
    __shared__ float qe[DK_];
    __shared__ float wl[M_];
    __shared__ float red[2];
    int q = blockIdx.x - (NQ_+1)*K_;
    if (tid < DK_) qe[tid] = qW[q*DK_ + tid];
    __syncthreads();
    if (tid < 50) {
        float acc = 0.f;
        const float* mk = Mk + tid*DK_;
        #pragma unroll 16
        for (int k = 0; k < DK_; k++) acc = fmaf(qe[k], mk[k], acc);
        wl[tid] = acc;
    } else if (tid < 100) {
        int j = tid - 50; float acc = 0.f;
        for (int k = 0; k < DK_; k++) acc = fmaf(qe[k], sW[(DV_+k)*DF_ + j], acc);
        g_Tsq[q*DF_ + j] = acc;
    } else if (tid < 104) {
        int c = tid - 100; float acc = tb[c];
        for (int k = 0; k < DK_; k++) acc = fmaf(qe[k], tW[k*4 + c], acc);
        g_Tbeta[q*4 + c] = acc;
    } else if (tid == 104) {
        float acc = db[0];
        for (int k = 0; k < DK_; k++) acc = fmaf(qe[k], dW[50 + k], acc);
        g_Tdisc[q] = acc;
    } else if (tid < 109) {
        int c = tid - 105; float acc = cb[c];
        for (int k = 0; k < DK_; k++) acc = fmaf(qe[k], cW[(50+k)*4 + c], acc);
        g_Tcorn[q*4 + c] = acc;
    }
    __syncthreads();
    if (tid == 0) {
        float mx = wl[0];
        for (int m = 1; m < M_; m++) mx = fmaxf(mx, wl[m]);
        red[0] = mx;
    }
    __syncthreads();
    if (tid < M_) wl[tid] = expf(wl[tid] - red[0]);
    __syncthreads();
    if (tid == 0) {
        float s = 0.f;
        for (int m = 0; m < M_; m++) s += wl[m];
        red[1] = 1.f / s;
    }
    __syncthreads();
    if (tid < M_) g_Tw[q*M_ + tid] = wl[tid] * red[1];
}

// ---------------- Scan v6 (settled design, ~487us): warp-private w, bf16 out -----
__global__ __launch_bounds__(128, 4) void scan_kernel(const int* __restrict__ qd,
                                                      const int* __restrict__ rd,
                                                      const float* __restrict__ Mv0) {
    __shared__ __align__(16) float w_s[4][2][52];
    int b    = blockIdx.y;
    int vb   = blockIdx.x;
    int tid  = threadIdx.x;
    int wid  = tid >> 5;
    int lane = tid & 31;
    int v    = vb*128 + tid;
    float* buf0 = &w_s[wid][0][0];
    float* buf1 = &w_s[wid][1][0];

    ull Mv2[25];
    #pragma unroll
    for (int j = 0; j < 25; j++)
        Mv2[j] = pack2(Mv0[(2*j)*DV_ + v], Mv0[(2*j+1)*DV_ + v]);

    const int bT = b * T_;
    const int* qp = qd + bT;
    const int* rp = rd + bT;
    __nv_bfloat16* rout = g_readsh + (size_t)bT * DV_ + v;
    bool lane2 = (lane < 18);

    int q0 = __ldg(qp+0), r0 = __ldg(rp+0);
    int q1 = __ldg(qp+1), r1 = __ldg(rp+1);
    int q2 = __ldg(qp+2), r2 = __ldg(rp+2);
    int q3 = __ldg(qp+3), r3 = __ldg(rp+3);
    buf0[lane] = g_Tw[q0*M_ + lane];
    if (lane2) buf0[lane+32] = g_Tw[q0*M_ + lane+32];
    float wA0 = g_Tw[q1*M_ + lane];
    float wA1 = lane2 ? g_Tw[q1*M_ + lane+32] : 0.f;
    float wB0 = g_Tw[q2*M_ + lane];
    float wB1 = lane2 ? g_Tw[q2*M_ + lane+32] : 0.f;
    float eA = g_Te[(q0*K_ + r0)*DV_ + v];
    float aA = g_Ta[(q0*K_ + r0)*DV_ + v];
    float eB = g_Te[(q1*K_ + r1)*DV_ + v];
    float aB = g_Ta[(q1*K_ + r1)*DV_ + v];

    for (int t = 0; t < T_; t++) {
        float* bw = ((t+1) & 1) ? buf1 : buf0;
        bw[lane] = wA0;
        if (lane2) bw[lane+32] = wA1;
        wA0 = wB0; wA1 = wB1;
        wB0 = g_Tw[q3*M_ + lane];
        if (lane2) wB1 = g_Tw[q3*M_ + lane+32];
        ull ne2 = pack2(-eA, -eA);
        ull a2  = pack2(aA,  aA);
        eA = eB; aA = aB;
        {
            int basen = (q2*K_ + r2)*DV_ + v;
            eB = g_Te[basen];
            aB = g_Ta[basen];
        }
        q2 = q3; r2 = r3;
        {
            int tn = t + 4; if (tn > T_-1) tn = T_-1;
            q3 = __ldg(qp + tn); r3 = __ldg(rp + tn);
        }
        __syncwarp(0xffffffffu);

        const float* wb = (t & 1) ? buf1 : buf0;
        ull acc0 = 0ull, acc1 = 0ull;
        #pragma unroll
        for (int j = 0; j < 12; j++) {
            ulonglong2 wv = *(const ulonglong2*)&wb[4*j];
            {
                ull old = Mv2[2*j];
                acc0 = fma2(wv.x, old, acc0);
                ull t1 = fma2(old, ne2, a2);
                Mv2[2*j] = fma2(wv.x, t1, old);
            }
            {
                ull old = Mv2[2*j+1];
                acc1 = fma2(wv.y, old, acc1);
                ull t1 = fma2(old, ne2, a2);
                Mv2[2*j+1] = fma2(wv.y, t1, old);
            }
        }
        {
            ull wlast = *(const ull*)&wb[48];
            ull old = Mv2[24];
            acc0 = fma2(wlast, old, acc0);
            ull t1 = fma2(old, ne2, a2);
            Mv2[24] = fma2(wlast, t1, old);
        }
        float lo, hi;
        unpack2(add2(acc0, acc1), lo, hi);
        rout[(size_t)t * DV_] = __float2bfloat16(lo + hi);
    }
}

// ---------------- Summary GEMM v5 (R15-proven, 99us): bf16 m16n8k16 + heads ------
#define ASTR 20
#define BTSTR 20
#define ABUF_U32 (128*ASTR)               // 2560
#define BBUF_U32 (64*BTSTR)               // 1280
#define SSUM_U32 (128*53)                 // 6784
#define POOL_U32 SSUM_U32
__global__ __launch_bounds__(256, 2) void summary_heads(const float* __restrict__ sW,
                                                        const float* __restrict__ sb,
                                                        const int* __restrict__ qd,
                                                        const float* __restrict__ abW,
                                                        const float* __restrict__ abB,
                                                        const float* __restrict__ dW,
                                                        const float* __restrict__ cW,
                                                        float* __restrict__ out) {
    __shared__ __align__(16) uint32_t pool[POOL_U32];
    __shared__ float sAb[DF_], sDw[DF_], sCw[DF_*4];
    uint32_t* As = pool;
    uint32_t* Bt = pool + ABUF_U32;
    float* sSum = (float*)pool;
    int tid = threadIdx.x;
    int w = tid >> 5, lane = tid & 31;
    int g = lane >> 2, t = lane & 3;
    int row0 = blockIdx.x * 128;

    if (tid < DF_)  { sAb[tid] = abW[tid]; sDw[tid] = dW[tid]; }
    if (tid < DF_*4) sCw[tid] = cW[tid];

    float acc[8][4];
    #pragma unroll
    for (int j = 0; j < 8; j++)
        #pragma unroll
        for (int c = 0; c < 4; c++) acc[j][c] = 0.f;

    int arow = tid >> 1, ahalf = (tid & 1) * 8;
    const uint32_t* agsrc = (const uint32_t*)(g_readsh + (size_t)(row0 + arow)*DV_) + ahalf;
    int bn = tid >> 2, bkp0 = (tid & 3) * 4;
    uint4 arv[2];
    uint32_t brv[4];

    arv[0] = *(const uint4*)(agsrc);
    arv[1] = *(const uint4*)(agsrc + 4);
    {
        #pragma unroll
        for (int u = 0; u < 4; u++) {
            int kk = 2*(bkp0 + u);
            float b0 = (bn < DF_) ? sW[kk*DF_ + bn] : 0.f;
            float b1 = (bn < DF_) ? sW[(kk+1)*DF_ + bn] : 0.f;
            brv[u] = bf16x2_(b0, b1);
        }
    }

    for (int ki = 0; ki < 8; ki++) {
        *(uint4*)(As + arow*ASTR + ahalf)     = arv[0];
        *(uint4*)(As + arow*ASTR + ahalf + 4) = arv[1];
        *(uint4*)(Bt + bn*BTSTR + bkp0)       = make_uint4(brv[0], brv[1], brv[2], brv[3]);
        __syncthreads();

        if (ki + 1 < 8) {
            const uint32_t* srcn = agsrc + (ki + 1)*16;
            arv[0] = *(const uint4*)(srcn);
            arv[1] = *(const uint4*)(srcn + 4);
            int k0n = (ki + 1) * 32;
            #pragma unroll
            for (int u = 0; u < 4; u++) {
                int kk = k0n + 2*(bkp0 + u);
                float b0 = (bn < DF_) ? sW[kk*DF_ + bn] : 0.f;
                float b1 = (bn < DF_) ? sW[(kk+1)*DF_ + bn] : 0.f;
                brv[u] = bf16x2_(b0, b1);
            }
        }

        #pragma unroll
        for (int s = 0; s < 2; s++) {
            int kp = 8*s;
            uint32_t a0 = As[(w*16 + g    )*ASTR + kp + t];
            uint32_t a1 = As[(w*16 + g + 8)*ASTR + kp + t];
            uint32_t a2 = As[(w*16 + g    )*ASTR + kp + t + 4];
            uint32_t a3 = As[(w*16 + g + 8)*ASTR + kp + t + 4];
            #pragma unroll
            for (int j = 0; j < 8; j++) {
                uint32_t b0 = Bt[(8*j + g)*BTSTR + kp + t];
                uint32_t b1 = Bt[(8*j + g)*BTSTR + kp + t + 4];
                asm volatile(
                    "mma.sync.aligned.m16n8k16.row.col.f32.bf16.bf16.f32 "
                    "{%0,%1,%2,%3}, {%4,%5,%6,%7}, {%8,%9}, {%0,%1,%2,%3};"
                    : "+f"(acc[j][0]), "+f"(acc[j][1]), "+f"(acc[j][2]), "+f"(acc[j][3])
                    : "r"(a0), "r"(a1), "r"(a2), "r"(a3), "r"(b0), "r"(b1));
            }
        }
        __syncthreads();
    }

    {
        int rA = w*16 + g, rB = rA + 8;
        int qA = qd[row0 + rA], qB = qd[row0 + rB];
        const float* tsqA = g_Tsq + qA*DF_;
        const float* tsqB = g_Tsq + qB*DF_;
        #pragma unroll
        for (int j = 0; j < 8; j++) {
            int n0 = 8*j + 2*t;
            #pragma unroll
            for (int c = 0; c < 2; c++) {
                int n = n0 + c;
                if (n < DF_) {
                    float bias = sb[n];
                    sSum[rA*53 + n] = tanhf(acc[j][c]     + tsqA[n] + bias);
                    sSum[rB*53 + n] = tanhf(acc[j][2 + c] + tsqB[n] + bias);
                }
            }
        }
    }
    __syncthreads();

    if (tid < 128) {
        int i = row0 + tid;
        int q = qd[i];
        float th = 0.f, ap = 0.f, l0 = 0.f, l1 = 0.f, l2 = 0.f, l3 = 0.f;
        #pragma unroll 10
        for (int k = 0; k < DF_; k++) {
            float s = sSum[tid*53 + k];
            th = fmaf(s, sAb[k], th);
            ap = fmaf(s, sDw[k], ap);
            l0 = fmaf(s, sCw[k*4+0], l0);
            l1 = fmaf(s, sCw[k*4+1], l1);
            l2 = fmaf(s, sCw[k*4+2], l2);
            l3 = fmaf(s, sCw[k*4+3], l3);
        }
        float theta = (th + __ldg(abB)) * 3.0f;
        ap += g_Tdisc[q];
        float alpha = (ap > 20.f) ? ap : log1pf(expf(ap));
        float4 tc = *(const float4*)&g_Tcorn[q*4];
        l0 += tc.x; l1 += tc.y; l2 += tc.z; l3 += tc.w;
        float cp0 = sigmoidf_(l0);
        float cp1 = cp0 * sigmoidf_(l1);
        float cp2 = cp1 * sigmoidf_(l2);
        float cp3 = cp2 * sigmoidf_(l3);
        const int BT = BT_;
        out[i] = theta;
        *(float4*)&out[BT + 4*i] = *(const float4*)&g_Tbeta[q*4];
        out[5*BT + i] = alpha;
        float* pp = out + 6*BT + 5*i;
        pp[0] = 1.f - cp0; pp[1] = cp0 - cp1; pp[2] = cp1 - cp2;
        pp[3] = cp2 - cp3; pp[4] = cp3;
        *(float4*)&out[11*BT + 4*i] = make_float4(l0, l1, l2, l3);
    }
}

// ---------------- launch ----------------
extern "C" void kernel_launch(void* const* d_in, const int* in_sizes, int n_in,
                              void* d_out, int out_size) {
    const int*   q_data    = (const int*)  d_in[0];
    const int*   r_data    = (const int*)  d_in[1];
    const float* q_embed_W = (const float*)d_in[2];
    const float* Mk        = (const float*)d_in[3];
    const float* Mv0       = (const float*)d_in[4];
    const float* value_W   = (const float*)d_in[5];
    const float* value_b   = (const float*)d_in[6];
    const float* erase_W   = (const float*)d_in[7];
    const float* erase_b   = (const float*)d_in[8];
    const float* add_W     = (const float*)d_in[9];
    const float* add_b     = (const float*)d_in[10];
    const float* summary_W = (const float*)d_in[11];
    const float* summary_b = (const float*)d_in[12];
    const float* ability_W = (const float*)d_in[13];
    const float* ability_b = (const float*)d_in[14];
    const float* thresh_W  = (const float*)d_in[15];
    const float* thresh_b  = (const float*)d_in[16];
    const float* disc_W    = (const float*)d_in[17];
    const float* disc_b    = (const float*)d_in[18];
    const float* corn_W    = (const float*)d_in[19];
    const float* corn_b    = (const float*)d_in[20];
    float* out = (float*)d_out;

    // Launch order: scan_kernel is my 3rd launch; gemm 4th (capture slot shifts
    // to gemm -- fine, both are characterized).
    p2_etables<<<126, 256>>>(value_W, erase_W, add_W, value_b, erase_b, add_b);
    p13_kernel<<<(NQ_+1)*K_ + (NQ_+1), 256>>>(q_embed_W, Mk, summary_W,
                                              thresh_W, thresh_b, disc_W, disc_b,
                                              corn_W, corn_b);
    scan_kernel<<<dim3(2, B_), 128>>>(q_data, r_data, Mv0);
    summary_heads<<<BT_/128, 256>>>(summary_W, summary_b, q_data,
                                    ability_W, ability_b, disc_W, corn_W, out);
}